// round 11
// baseline (speedup 1.0000x reference)
#include <cuda_runtime.h>
#include <cuda_bf16.h>

#define DM   1024
#define HEADS 16
#define DH    64
#define POS  2048
#define BATCH 2
#define TOK  (BATCH*POS)   // 4096

// ---------------- scratch (device globals: allocation-free) ----------------
__device__ __nv_bfloat16 g_Xh[TOK*DM], g_Xl[TOK*DM];
__device__ __nv_bfloat16 g_Qh[TOK*DM], g_Ql[TOK*DM];
__device__ __nv_bfloat16 g_Kh[TOK*DM], g_Kl[TOK*DM];
__device__ __nv_bfloat16 g_Vh[TOK*DM], g_Vl[TOK*DM];
__device__ __nv_bfloat16 g_Ah[TOK*DM], g_Al[TOK*DM];
__device__ __nv_bfloat16 g_Wqh[DM*DM], g_Wql[DM*DM];
__device__ __nv_bfloat16 g_Wkh[DM*DM], g_Wkl[DM*DM];
__device__ __nv_bfloat16 g_Wvh[DM*DM], g_Wvl[DM*DM];
__device__ __nv_bfloat16 g_Woh[DM*DM], g_Wol[DM*DM];

// ---------------- helpers ----------------
__device__ __forceinline__ unsigned smem_u32(const void* p) {
    unsigned r;
    asm("{ .reg .u64 t; cvta.to.shared.u64 t, %1; cvt.u32.u64 %0, t; }" : "=r"(r) : "l"(p));
    return r;
}
__device__ __forceinline__ void cp16(unsigned s, const void* g) {
    asm volatile("cp.async.cg.shared.global [%0], [%1], 16;" :: "r"(s), "l"(g) : "memory");
}
#define CP_ASYNC_COMMIT() asm volatile("cp.async.commit_group;" ::: "memory")
#define CP_ASYNC_WAIT1()  asm volatile("cp.async.wait_group 1;" ::: "memory")
#define CP_ASYNC_WAIT0()  asm volatile("cp.async.wait_group 0;" ::: "memory")

__device__ __forceinline__ void ldsm4(unsigned* r, unsigned a) {
    asm volatile("ldmatrix.sync.aligned.m8n8.x4.shared.b16 {%0,%1,%2,%3}, [%4];"
        : "=r"(r[0]), "=r"(r[1]), "=r"(r[2]), "=r"(r[3]) : "r"(a));
}
__device__ __forceinline__ void ldsm2(unsigned* r, unsigned a) {
    asm volatile("ldmatrix.sync.aligned.m8n8.x2.shared.b16 {%0,%1}, [%2];"
        : "=r"(r[0]), "=r"(r[1]) : "r"(a));
}
__device__ __forceinline__ void ldsm2t(unsigned* r, unsigned a) {
    asm volatile("ldmatrix.sync.aligned.m8n8.x2.trans.shared.b16 {%0,%1}, [%2];"
        : "=r"(r[0]), "=r"(r[1]) : "r"(a));
}
__device__ __forceinline__ void mma_bf16(float* d, const unsigned* a, const unsigned* b) {
    asm volatile("mma.sync.aligned.m16n8k16.row.col.f32.bf16.bf16.f32 "
        "{%0,%1,%2,%3}, {%4,%5,%6,%7}, {%8,%9}, {%0,%1,%2,%3};"
        : "+f"(d[0]), "+f"(d[1]), "+f"(d[2]), "+f"(d[3])
        : "r"(a[0]), "r"(a[1]), "r"(a[2]), "r"(a[3]), "r"(b[0]), "r"(b[1]));
}
__device__ __forceinline__ unsigned pkbf(float a, float b) {
    __nv_bfloat162 t2 = __halves2bfloat162(__float2bfloat16(a), __float2bfloat16(b));
    return *(unsigned*)&t2;
}

// ---------------- fp32 -> bf16 hi/lo split kernels ----------------
__global__ void split_f32(const float4* __restrict__ src,
                          __nv_bfloat162* __restrict__ h, __nv_bfloat162* __restrict__ l, int n4)
{
    int i = blockIdx.x * blockDim.x + threadIdx.x;
    if (i >= n4) return;
    float4 v = src[i];
    __nv_bfloat16 hx = __float2bfloat16(v.x);
    __nv_bfloat16 hy = __float2bfloat16(v.y);
    __nv_bfloat16 hz = __float2bfloat16(v.z);
    __nv_bfloat16 hw = __float2bfloat16(v.w);
    h[i*2+0] = __halves2bfloat162(hx, hy);
    h[i*2+1] = __halves2bfloat162(hz, hw);
    l[i*2+0] = __halves2bfloat162(__float2bfloat16(v.x - __bfloat162float(hx)),
                                  __float2bfloat16(v.y - __bfloat162float(hy)));
    l[i*2+1] = __halves2bfloat162(__float2bfloat16(v.z - __bfloat162float(hz)),
                                  __float2bfloat16(v.w - __bfloat162float(hw)));
}

// Fused weight transpose+split (all 4 matrices in one launch, z selects).
// z<3 (QKV layout): src (k,n) = W[n>>6][k][n&63].  z=3 (out): src (k,n) = W[k*DM+n].
__global__ __launch_bounds__(1024)
void split_w_all(const float* __restrict__ Wq, const float* __restrict__ Wk,
                 const float* __restrict__ Wv, const float* __restrict__ Wo,
                 __nv_bfloat16* __restrict__ Hq, __nv_bfloat16* __restrict__ Lq,
                 __nv_bfloat16* __restrict__ Hk, __nv_bfloat16* __restrict__ Lk,
                 __nv_bfloat16* __restrict__ Hv, __nv_bfloat16* __restrict__ Lv,
                 __nv_bfloat16* __restrict__ Ho, __nv_bfloat16* __restrict__ Lo)
{
    __shared__ float tile[32][33];
    int z = blockIdx.z;
    const float* W = (z == 0) ? Wq : (z == 1) ? Wk : (z == 2) ? Wv : Wo;
    __nv_bfloat16* h = (z == 0) ? Hq : (z == 1) ? Hk : (z == 2) ? Hv : Ho;
    __nv_bfloat16* l = (z == 0) ? Lq : (z == 1) ? Lk : (z == 2) ? Lv : Lo;
    int n0 = blockIdx.x * 32, k0 = blockIdx.y * 32;
    int tx = threadIdx.x & 31, ty = threadIdx.x >> 5;
    {
        int n = n0 + tx, k = k0 + ty;
        float x = (z < 3) ? W[(size_t)(n >> 6) * (DM * DH) + (size_t)k * DH + (n & 63)]
                          : W[(size_t)k * DM + n];
        tile[ty][tx] = x;
    }
    __syncthreads();
    {
        int n = n0 + ty, k = k0 + tx;
        float x = tile[tx][ty];
        __nv_bfloat16 hi = __float2bfloat16(x);
        size_t o = (size_t)n * DM + k;
        h[o] = hi;
        l[o] = __float2bfloat16(x - __bfloat162float(hi));
    }
}

// ---------------- HMMA split-bf16 GEMM: O[4096x1024] = A x B^T ----------------
// MODE 0: epilogue writes bf16 hi/lo (QKV path). MODE 1: fp32 (out-proj).
#define TILE_B   10240
#define STAGE_B  40960
#define NCHUNK   32
#define GEMM_SMEM_BYTES (2*STAGE_B)

template<int MODE>
__global__ __launch_bounds__(256, 2)
void mma_gemm(const __nv_bfloat16* __restrict__ Ah, const __nv_bfloat16* __restrict__ Al,
              const __nv_bfloat16* __restrict__ B0h, const __nv_bfloat16* __restrict__ B0l,
              const __nv_bfloat16* __restrict__ B1h, const __nv_bfloat16* __restrict__ B1l,
              const __nv_bfloat16* __restrict__ B2h, const __nv_bfloat16* __restrict__ B2l,
              float* __restrict__ Of,
              __nv_bfloat16* O0h, __nv_bfloat16* O0l,
              __nv_bfloat16* O1h, __nv_bfloat16* O1l,
              __nv_bfloat16* O2h, __nv_bfloat16* O2l)
{
    extern __shared__ __align__(128) char smem[];
    const unsigned sb = smem_u32(smem);
    int tid = threadIdx.x, lane = tid & 31, wid = tid >> 5;
    int n0 = blockIdx.x * 128, m0 = blockIdx.y * 128;
    int z = blockIdx.z;
    const char* pAh = (const char*)Ah;
    const char* pAl = (const char*)Al;
    const char* pBh = (const char*)((z == 0) ? B0h : (z == 1) ? B1h : B2h);
    const char* pBl = (const char*)((z == 0) ? B0l : (z == 1) ? B1l : B2l);
    __nv_bfloat16* Oh = (z == 0) ? O0h : (z == 1) ? O1h : O2h;
    __nv_bfloat16* Ol = (z == 0) ? O0l : (z == 1) ? O1l : O2l;

    int wm = (wid & 1) * 64;
    int wn = (wid >> 1) * 32;
    int lrow = tid >> 2;
    int lcol = (tid & 3) * 16;

    float acc[4][4][4];
#pragma unroll
    for (int mi = 0; mi < 4; mi++)
#pragma unroll
        for (int ni = 0; ni < 4; ni++)
#pragma unroll
            for (int e = 0; e < 4; e++) acc[mi][ni][e] = 0.0f;

    auto load_chunk = [&](int c, int st) {
        int k0b = c * 64;
#pragma unroll
        for (int half = 0; half < 2; half++) {
            int row = lrow + half * 64;
            unsigned sa = sb + st * STAGE_B + row * 80 + lcol;
            size_t goffA = ((size_t)(m0 + row) * DM) * 2 + k0b + lcol;
            size_t goffB = ((size_t)(n0 + row) * DM) * 2 + k0b + lcol;
            cp16(sa,              pAh + goffA);
            cp16(sa + TILE_B,     pAl + goffA);
            cp16(sa + 2*TILE_B,   pBh + goffB);
            cp16(sa + 3*TILE_B,   pBl + goffB);
        }
    };

    load_chunk(0, 0);
    CP_ASYNC_COMMIT();

    unsigned a_base = (wm + (lane & 15)) * 80 + ((lane >> 4) << 4);
    unsigned b_base = 2*TILE_B + (wn + (lane & 7)) * 80 + (((lane >> 3) & 1) << 4);

    for (int c = 0; c < NCHUNK; c++) {
        if (c + 1 < NCHUNK) {
            load_chunk(c + 1, (c + 1) & 1);
            CP_ASYNC_COMMIT();
            CP_ASYNC_WAIT1();
        } else {
            CP_ASYNC_WAIT0();
        }
        __syncthreads();

        unsigned stb = sb + (c & 1) * STAGE_B;
#pragma unroll
        for (int ks = 0; ks < 2; ks++) {
            unsigned af[4][4], bh[4][2], bl[4][2];
            unsigned ka = stb + ks * 32;
#pragma unroll
            for (int mi = 0; mi < 4; mi++) ldsm4(af[mi], ka + a_base + mi * (16 * 80));
#pragma unroll
            for (int ni = 0; ni < 4; ni++) {
                ldsm2(bh[ni], ka + b_base + ni * (8 * 80));
                ldsm2(bl[ni], ka + b_base + TILE_B + ni * (8 * 80));
            }
#pragma unroll
            for (int mi = 0; mi < 4; mi++)
#pragma unroll
                for (int ni = 0; ni < 4; ni++) mma_bf16(acc[mi][ni], af[mi], bh[ni]);
#pragma unroll
            for (int mi = 0; mi < 4; mi++)
#pragma unroll
                for (int ni = 0; ni < 4; ni++) mma_bf16(acc[mi][ni], af[mi], bl[ni]);
#pragma unroll
            for (int mi = 0; mi < 4; mi++) ldsm4(af[mi], ka + a_base + TILE_B + mi * (16 * 80));
#pragma unroll
            for (int mi = 0; mi < 4; mi++)
#pragma unroll
                for (int ni = 0; ni < 4; ni++) mma_bf16(acc[mi][ni], af[mi], bh[ni]);
        }
        __syncthreads();
    }

    int g = lane >> 2, t = lane & 3;
#pragma unroll
    for (int mi = 0; mi < 4; mi++) {
#pragma unroll
        for (int ni = 0; ni < 4; ni++) {
            int row = m0 + wm + mi * 16 + g;
            int col = n0 + wn + ni * 8 + t * 2;
            if (MODE == 1) {
                float2 v0 = { acc[mi][ni][0], acc[mi][ni][1] };
                float2 v1 = { acc[mi][ni][2], acc[mi][ni][3] };
                *(float2*)(Of + (size_t)row * DM + col)       = v0;
                *(float2*)(Of + (size_t)(row + 8) * DM + col) = v1;
            } else {
#pragma unroll
                for (int rr = 0; rr < 2; rr++) {
                    float vx = acc[mi][ni][rr*2], vy = acc[mi][ni][rr*2+1];
                    __nv_bfloat16 hx = __float2bfloat16(vx);
                    __nv_bfloat16 hy = __float2bfloat16(vy);
                    size_t off = (size_t)(row + rr*8) * DM + col;
                    *(__nv_bfloat162*)(Oh + off) = __halves2bfloat162(hx, hy);
                    *(__nv_bfloat162*)(Ol + off) = __halves2bfloat162(
                        __float2bfloat16(vx - __bfloat162float(hx)),
                        __float2bfloat16(vy - __bfloat162float(hy)));
                }
            }
        }
    }
}

// ---------------- HMMA flash attention (causal) ----------------
// CTA: 128 queries x (b,h). 8 warps, warp = 16 query rows x full 64-key block.
// S = Qh*Kh (1 term).  PV = Ph*Vh + Pl*Vh + Ph*Vl (3 terms).
// P hi/lo packed inside the PV loop (no persistent frag arrays) -> fits 128 regs, occ 2.
#define AQ   128
#define AKB  64
#define QST  144
#define KST  144
#define Q_TILE   (AQ*QST)       // 18432
#define KV_TILE  (AKB*KST)      // 9216
#define KV_STAGE (3*KV_TILE)    // 27648
#define ATTN_SMEM (Q_TILE + 2*KV_STAGE)  // 73728

__global__ __launch_bounds__(256, 2)
void attn_mma()
{
    extern __shared__ __align__(128) char smem[];
    const unsigned sb = smem_u32(smem);
    int tid = threadIdx.x, lane = tid & 31, w = tid >> 5;
    int g = lane >> 2, t = lane & 3;
    int qt = (int)gridDim.x - 1 - (int)blockIdx.x;   // big tiles first
    int h = blockIdx.y, b = blockIdx.z;
    int q0 = qt * AQ;
    const char* pQh = (const char*)g_Qh;
    const char* pKh = (const char*)g_Kh;
    const char* pVh = (const char*)g_Vh;
    const char* pVl = (const char*)g_Vl;

    // stage Q tile (128 rows x 128B)
#pragma unroll
    for (int i = 0; i < 4; i++) {
        int idx = tid + 256 * i;          // 0..1023
        int row = idx >> 3, c16 = idx & 7;
        size_t off = ((size_t)(b * POS + q0 + row) * DM + h * DH) * 2 + c16 * 16;
        cp16(sb + row * QST + c16 * 16, pQh + off);
    }

    auto load_kv = [&](int kb, int st) {
        int k0 = kb * AKB;
        unsigned base = sb + Q_TILE + st * KV_STAGE;
#pragma unroll
        for (int i = 0; i < 2; i++) {
            int idx = tid + 256 * i;      // 0..511
            int row = idx >> 3, c16 = idx & 7;
            size_t off = ((size_t)(b * POS + k0 + row) * DM + h * DH) * 2 + c16 * 16;
            unsigned d = base + row * KST + c16 * 16;
            cp16(d,               pKh + off);
            cp16(d + KV_TILE,     pVh + off);
            cp16(d + 2*KV_TILE,   pVl + off);
        }
    };

    load_kv(0, 0);
    CP_ASYNC_COMMIT();

    int nkb = 2 * (qt + 1);
    int qr0 = q0 + 16 * w + g;            // this thread's first query row
    float m0 = -1e30f, m1 = -1e30f, l0 = 0.0f, l1 = 0.0f;
    float o[8][4];
#pragma unroll
    for (int ni = 0; ni < 8; ni++)
#pragma unroll
        for (int e = 0; e < 4; e++) o[ni][e] = 0.0f;

    unsigned qf[4][4];
    unsigned qa = sb + (16 * w + (lane & 15)) * QST + ((lane >> 4) << 4);

    for (int kb = 0; kb < nkb; kb++) {
        if (kb + 1 < nkb) {
            load_kv(kb + 1, (kb + 1) & 1);
            CP_ASYNC_COMMIT();
            CP_ASYNC_WAIT1();
        } else {
            CP_ASYNC_WAIT0();
        }
        __syncthreads();
        if (kb == 0) {                    // Q is resident after first wait
#pragma unroll
            for (int ks = 0; ks < 4; ks++) ldsm4(qf[ks], qa + ks * 32);
        }

        unsigned stg = sb + Q_TILE + (kb & 1) * KV_STAGE;
        int k0 = kb * AKB;
        if (k0 <= q0 + 16 * w + 15) {     // warp has unmasked rows in this block
            // ---- S = Qh * Kh^T ----
            float s[8][4];
#pragma unroll
            for (int ni = 0; ni < 8; ni++)
#pragma unroll
                for (int e = 0; e < 4; e++) s[ni][e] = 0.0f;
            unsigned kbse = stg + (lane & 7) * KST + (((lane >> 3) & 1) << 4);
#pragma unroll
            for (int ks = 0; ks < 4; ks++)
#pragma unroll
                for (int ni = 0; ni < 8; ni++) {
                    unsigned bf[2];
                    ldsm2(bf, kbse + ni * (8 * KST) + ks * 32);
                    mma_bf16(s[ni], qf[ks], bf);
                }
            // ---- scale + causal mask ----
#pragma unroll
            for (int ni = 0; ni < 8; ni++)
#pragma unroll
                for (int e = 0; e < 4; e++) s[ni][e] *= 0.125f;
            if (k0 + 63 > qr0) {
#pragma unroll
                for (int ni = 0; ni < 8; ni++) {
                    int kc = k0 + ni * 8 + t * 2;
                    if (kc     > qr0)     s[ni][0] = -1e30f;
                    if (kc + 1 > qr0)     s[ni][1] = -1e30f;
                    if (kc     > qr0 + 8) s[ni][2] = -1e30f;
                    if (kc + 1 > qr0 + 8) s[ni][3] = -1e30f;
                }
            }
            // ---- online softmax (warp-local, rows g and g+8) ----
            float bm0 = -1e30f, bm1 = -1e30f;
#pragma unroll
            for (int ni = 0; ni < 8; ni++) {
                bm0 = fmaxf(bm0, fmaxf(s[ni][0], s[ni][1]));
                bm1 = fmaxf(bm1, fmaxf(s[ni][2], s[ni][3]));
            }
            bm0 = fmaxf(bm0, __shfl_xor_sync(0xffffffffu, bm0, 1));
            bm0 = fmaxf(bm0, __shfl_xor_sync(0xffffffffu, bm0, 2));
            bm1 = fmaxf(bm1, __shfl_xor_sync(0xffffffffu, bm1, 1));
            bm1 = fmaxf(bm1, __shfl_xor_sync(0xffffffffu, bm1, 2));
            float mn0 = fmaxf(m0, bm0), mn1 = fmaxf(m1, bm1);
            float a0 = __expf(m0 - mn0), a1 = __expf(m1 - mn1);
            m0 = mn0; m1 = mn1;
            float bs0 = 0.0f, bs1 = 0.0f;
#pragma unroll
            for (int ni = 0; ni < 8; ni++) {
                float p0 = __expf(s[ni][0] - m0), p1 = __expf(s[ni][1] - m0);
                float p2 = __expf(s[ni][2] - m1), p3 = __expf(s[ni][3] - m1);
                bs0 += p0 + p1; bs1 += p2 + p3;
                s[ni][0] = p0; s[ni][1] = p1; s[ni][2] = p2; s[ni][3] = p3;
            }
            bs0 += __shfl_xor_sync(0xffffffffu, bs0, 1);
            bs0 += __shfl_xor_sync(0xffffffffu, bs0, 2);
            bs1 += __shfl_xor_sync(0xffffffffu, bs1, 1);
            bs1 += __shfl_xor_sync(0xffffffffu, bs1, 2);
            l0 = l0 * a0 + bs0;
            l1 = l1 * a1 + bs1;
#pragma unroll
            for (int ni = 0; ni < 8; ni++) {
                o[ni][0] *= a0; o[ni][1] *= a0;
                o[ni][2] *= a1; o[ni][3] *= a1;
            }
            // ---- O += P * V (3 split terms); P hi/lo packed in-loop ----
            unsigned vbse = stg + KV_TILE + (lane & 15) * KST;
#pragma unroll
            for (int ks = 0; ks < 4; ks++) {
                unsigned aH[4], aL[4];
#pragma unroll
                for (int half = 0; half < 2; half++) {
                    int ni2 = 2 * ks + half;
#pragma unroll
                    for (int rr = 0; rr < 2; rr++) {
                        float vx = s[ni2][rr*2], vy = s[ni2][rr*2+1];
                        __nv_bfloat16 hx = __float2bfloat16(vx);
                        __nv_bfloat16 hy = __float2bfloat16(vy);
                        __nv_bfloat162 hp = __halves2bfloat162(hx, hy);
                        aH[half*2+rr] = *(unsigned*)&hp;
                        aL[half*2+rr] = pkbf(vx - __bfloat162float(hx), vy - __bfloat162float(hy));
                    }
                }
#pragma unroll
                for (int ni = 0; ni < 8; ni++) {
                    unsigned bh[2], bl[2];
                    ldsm2t(bh, vbse + ks * (16 * KST) + ni * 16);
                    ldsm2t(bl, vbse + KV_TILE + ks * (16 * KST) + ni * 16);
                    mma_bf16(o[ni], aH, bh);
                    mma_bf16(o[ni], aL, bh);
                    mma_bf16(o[ni], aH, bl);
                }
            }
        }
        __syncthreads();
    }

    // ---- finalize: O/l, write bf16 hi/lo concat layout [b,p,h,d] ----
    float inv0 = 1.0f / l0, inv1 = 1.0f / l1;
    size_t r0off = (size_t)(b * POS + qr0) * DM + h * DH;
    size_t r1off = r0off + (size_t)8 * DM;
#pragma unroll
    for (int ni = 0; ni < 8; ni++) {
        int col = ni * 8 + t * 2;
        float vx = o[ni][0] * inv0, vy = o[ni][1] * inv0;
        __nv_bfloat16 hx = __float2bfloat16(vx), hy = __float2bfloat16(vy);
        *(__nv_bfloat162*)(g_Ah + r0off + col) = __halves2bfloat162(hx, hy);
        *(__nv_bfloat162*)(g_Al + r0off + col) = __halves2bfloat162(
            __float2bfloat16(vx - __bfloat162float(hx)),
            __float2bfloat16(vy - __bfloat162float(hy)));
        float wx = o[ni][2] * inv1, wy = o[ni][3] * inv1;
        __nv_bfloat16 gx = __float2bfloat16(wx), gy = __float2bfloat16(wy);
        *(__nv_bfloat162*)(g_Ah + r1off + col) = __halves2bfloat162(gx, gy);
        *(__nv_bfloat162*)(g_Al + r1off + col) = __halves2bfloat162(
            __float2bfloat16(wx - __bfloat162float(gx)),
            __float2bfloat16(wy - __bfloat162float(gy)));
    }
}

// ---------------- launch ----------------
extern "C" void kernel_launch(void* const* d_in, const int* in_sizes, int n_in,
                              void* d_out, int out_size)
{
    (void)in_sizes; (void)n_in; (void)out_size;
    const float* X  = (const float*)d_in[0];
    const float* Wq = (const float*)d_in[1];
    const float* Wk = (const float*)d_in[2];
    const float* Wv = (const float*)d_in[3];
    const float* Wo = (const float*)d_in[4];
    float* out = (float*)d_out;

    __nv_bfloat16 *Xh, *Xl, *Qh, *Ql, *Kh, *Kl, *Vh, *Vl, *Aah, *Aal;
    __nv_bfloat16 *Wqh, *Wql, *Wkh, *Wkl, *Wvh, *Wvl, *Woh, *Wol;
    cudaGetSymbolAddress((void**)&Xh,  g_Xh);  cudaGetSymbolAddress((void**)&Xl,  g_Xl);
    cudaGetSymbolAddress((void**)&Qh,  g_Qh);  cudaGetSymbolAddress((void**)&Ql,  g_Ql);
    cudaGetSymbolAddress((void**)&Kh,  g_Kh);  cudaGetSymbolAddress((void**)&Kl,  g_Kl);
    cudaGetSymbolAddress((void**)&Vh,  g_Vh);  cudaGetSymbolAddress((void**)&Vl,  g_Vl);
    cudaGetSymbolAddress((void**)&Aah, g_Ah);  cudaGetSymbolAddress((void**)&Aal, g_Al);
    cudaGetSymbolAddress((void**)&Wqh, g_Wqh); cudaGetSymbolAddress((void**)&Wql, g_Wql);
    cudaGetSymbolAddress((void**)&Wkh, g_Wkh); cudaGetSymbolAddress((void**)&Wkl, g_Wkl);
    cudaGetSymbolAddress((void**)&Wvh, g_Wvh); cudaGetSymbolAddress((void**)&Wvl, g_Wvl);
    cudaGetSymbolAddress((void**)&Woh, g_Woh); cudaGetSymbolAddress((void**)&Wol, g_Wol);

    cudaFuncSetAttribute(mma_gemm<0>, cudaFuncAttributeMaxDynamicSharedMemorySize, GEMM_SMEM_BYTES);
    cudaFuncSetAttribute(mma_gemm<1>, cudaFuncAttributeMaxDynamicSharedMemorySize, GEMM_SMEM_BYTES);
    cudaFuncSetAttribute(attn_mma,    cudaFuncAttributeMaxDynamicSharedMemorySize, ATTN_SMEM);

    // 0) precision splits of inputs (weights fused into one launch)
    int n4 = TOK * DM / 4;
    split_f32<<<(n4 + 255) / 256, 256>>>((const float4*)X, (__nv_bfloat162*)Xh, (__nv_bfloat162*)Xl, n4);
    dim3 gw(DM / 32, DM / 32, 4);
    split_w_all<<<gw, 1024>>>(Wq, Wk, Wv, Wo, Wqh, Wql, Wkh, Wkl, Wvh, Wvl, Woh, Wol);

    // 1) fused QKV projection -> bf16 hi/lo Q,K,V directly
    dim3 g1(DM / 128, TOK / 128, 3);
    mma_gemm<0><<<g1, 256, GEMM_SMEM_BYTES>>>(Xh, Xl, Wqh, Wql, Wkh, Wkl, Wvh, Wvl,
                                              nullptr, Qh, Ql, Kh, Kl, Vh, Vl);

    // 2) causal flash attention on tensor cores -> bf16 hi/lo A directly
    dim3 g2(POS / AQ, HEADS, BATCH);
    attn_mma<<<g2, 256, ATTN_SMEM>>>();

    // 3) out projection -> fp32 output
    dim3 g3(DM / 128, TOK / 128, 1);
    mma_gemm<1><<<g3, 256, GEMM_SMEM_BYTES>>>(Aah, Aal, Woh, Wol, nullptr, nullptr, nullptr, nullptr,
                                              out, nullptr, nullptr, nullptr, nullptr, nullptr, nullptr);
}

// round 12
// speedup vs baseline: 1.1415x; 1.1415x over previous
#include <cuda_runtime.h>
#include <cuda_bf16.h>
#include <cuda_fp16.h>

#define DM   1024
#define HEADS 16
#define DH    64
#define POS  2048
#define BATCH 2
#define TOK  (BATCH*POS)   // 4096

// ---------------- scratch (device globals: allocation-free) ----------------
__device__ __nv_bfloat16 g_Xh[TOK*DM], g_Xl[TOK*DM];
__device__ __half        g_Qf[TOK*DM], g_Kf[TOK*DM], g_Vf[TOK*DM];
__device__ __nv_bfloat16 g_Ah[TOK*DM], g_Al[TOK*DM];
__device__ __nv_bfloat16 g_Wqh[DM*DM], g_Wql[DM*DM];
__device__ __nv_bfloat16 g_Wkh[DM*DM], g_Wkl[DM*DM];
__device__ __nv_bfloat16 g_Wvh[DM*DM], g_Wvl[DM*DM];
__device__ __nv_bfloat16 g_Woh[DM*DM], g_Wol[DM*DM];

// ---------------- helpers ----------------
__device__ __forceinline__ unsigned smem_u32(const void* p) {
    unsigned r;
    asm("{ .reg .u64 t; cvta.to.shared.u64 t, %1; cvt.u32.u64 %0, t; }" : "=r"(r) : "l"(p));
    return r;
}
__device__ __forceinline__ void cp16(unsigned s, const void* g) {
    asm volatile("cp.async.cg.shared.global [%0], [%1], 16;" :: "r"(s), "l"(g) : "memory");
}
#define CP_ASYNC_COMMIT() asm volatile("cp.async.commit_group;" ::: "memory")
#define CP_ASYNC_WAIT1()  asm volatile("cp.async.wait_group 1;" ::: "memory")
#define CP_ASYNC_WAIT0()  asm volatile("cp.async.wait_group 0;" ::: "memory")

__device__ __forceinline__ void ldsm4(unsigned* r, unsigned a) {
    asm volatile("ldmatrix.sync.aligned.m8n8.x4.shared.b16 {%0,%1,%2,%3}, [%4];"
        : "=r"(r[0]), "=r"(r[1]), "=r"(r[2]), "=r"(r[3]) : "r"(a));
}
__device__ __forceinline__ void ldsm2(unsigned* r, unsigned a) {
    asm volatile("ldmatrix.sync.aligned.m8n8.x2.shared.b16 {%0,%1}, [%2];"
        : "=r"(r[0]), "=r"(r[1]) : "r"(a));
}
__device__ __forceinline__ void ldsm4t(unsigned* r, unsigned a) {
    asm volatile("ldmatrix.sync.aligned.m8n8.x4.trans.shared.b16 {%0,%1,%2,%3}, [%4];"
        : "=r"(r[0]), "=r"(r[1]), "=r"(r[2]), "=r"(r[3]) : "r"(a));
}
__device__ __forceinline__ void mma_bf16(float* d, const unsigned* a, const unsigned* b) {
    asm volatile("mma.sync.aligned.m16n8k16.row.col.f32.bf16.bf16.f32 "
        "{%0,%1,%2,%3}, {%4,%5,%6,%7}, {%8,%9}, {%0,%1,%2,%3};"
        : "+f"(d[0]), "+f"(d[1]), "+f"(d[2]), "+f"(d[3])
        : "r"(a[0]), "r"(a[1]), "r"(a[2]), "r"(a[3]), "r"(b[0]), "r"(b[1]));
}
__device__ __forceinline__ void mma_f16(float* d, const unsigned* a, const unsigned* b) {
    asm volatile("mma.sync.aligned.m16n8k16.row.col.f32.f16.f16.f32 "
        "{%0,%1,%2,%3}, {%4,%5,%6,%7}, {%8,%9}, {%0,%1,%2,%3};"
        : "+f"(d[0]), "+f"(d[1]), "+f"(d[2]), "+f"(d[3])
        : "r"(a[0]), "r"(a[1]), "r"(a[2]), "r"(a[3]), "r"(b[0]), "r"(b[1]));
}
__device__ __forceinline__ unsigned pkh(float a, float b) {
    __half2 t = __floats2half2_rn(a, b);
    return *(unsigned*)&t;
}

// ---------------- fp32 -> bf16 hi/lo split kernels ----------------
__global__ void split_f32(const float4* __restrict__ src,
                          __nv_bfloat162* __restrict__ h, __nv_bfloat162* __restrict__ l, int n4)
{
    int i = blockIdx.x * blockDim.x + threadIdx.x;
    if (i >= n4) return;
    float4 v = src[i];
    __nv_bfloat16 hx = __float2bfloat16(v.x);
    __nv_bfloat16 hy = __float2bfloat16(v.y);
    __nv_bfloat16 hz = __float2bfloat16(v.z);
    __nv_bfloat16 hw = __float2bfloat16(v.w);
    h[i*2+0] = __halves2bfloat162(hx, hy);
    h[i*2+1] = __halves2bfloat162(hz, hw);
    l[i*2+0] = __halves2bfloat162(__float2bfloat16(v.x - __bfloat162float(hx)),
                                  __float2bfloat16(v.y - __bfloat162float(hy)));
    l[i*2+1] = __halves2bfloat162(__float2bfloat16(v.z - __bfloat162float(hz)),
                                  __float2bfloat16(v.w - __bfloat162float(hw)));
}

// Fused weight transpose+split (all 4 matrices in one launch, z selects).
__global__ __launch_bounds__(1024)
void split_w_all(const float* __restrict__ Wq, const float* __restrict__ Wk,
                 const float* __restrict__ Wv, const float* __restrict__ Wo,
                 __nv_bfloat16* __restrict__ Hq, __nv_bfloat16* __restrict__ Lq,
                 __nv_bfloat16* __restrict__ Hk, __nv_bfloat16* __restrict__ Lk,
                 __nv_bfloat16* __restrict__ Hv, __nv_bfloat16* __restrict__ Lv,
                 __nv_bfloat16* __restrict__ Ho, __nv_bfloat16* __restrict__ Lo)
{
    __shared__ float tile[32][33];
    int z = blockIdx.z;
    const float* W = (z == 0) ? Wq : (z == 1) ? Wk : (z == 2) ? Wv : Wo;
    __nv_bfloat16* h = (z == 0) ? Hq : (z == 1) ? Hk : (z == 2) ? Hv : Ho;
    __nv_bfloat16* l = (z == 0) ? Lq : (z == 1) ? Lk : (z == 2) ? Lv : Lo;
    int n0 = blockIdx.x * 32, k0 = blockIdx.y * 32;
    int tx = threadIdx.x & 31, ty = threadIdx.x >> 5;
    {
        int n = n0 + tx, k = k0 + ty;
        float x = (z < 3) ? W[(size_t)(n >> 6) * (DM * DH) + (size_t)k * DH + (n & 63)]
                          : W[(size_t)k * DM + n];
        tile[ty][tx] = x;
    }
    __syncthreads();
    {
        int n = n0 + ty, k = k0 + tx;
        float x = tile[tx][ty];
        __nv_bfloat16 hi = __float2bfloat16(x);
        size_t o = (size_t)n * DM + k;
        h[o] = hi;
        l[o] = __float2bfloat16(x - __bfloat162float(hi));
    }
}

// ---------------- HMMA split-bf16 GEMM: O[4096x1024] = A x B^T ----------------
// MODE 0: epilogue writes single fp16 (Q/K/V for attention). MODE 1: fp32 (out-proj).
#define TILE_B   10240
#define STAGE_B  40960
#define NCHUNK   32
#define GEMM_SMEM_BYTES (2*STAGE_B)

template<int MODE>
__global__ __launch_bounds__(256, 2)
void mma_gemm(const __nv_bfloat16* __restrict__ Ah, const __nv_bfloat16* __restrict__ Al,
              const __nv_bfloat16* __restrict__ B0h, const __nv_bfloat16* __restrict__ B0l,
              const __nv_bfloat16* __restrict__ B1h, const __nv_bfloat16* __restrict__ B1l,
              const __nv_bfloat16* __restrict__ B2h, const __nv_bfloat16* __restrict__ B2l,
              float* __restrict__ Of,
              __half* O0f, __half* O1f, __half* O2f)
{
    extern __shared__ __align__(128) char smem[];
    const unsigned sb = smem_u32(smem);
    int tid = threadIdx.x, lane = tid & 31, wid = tid >> 5;
    int n0 = blockIdx.x * 128, m0 = blockIdx.y * 128;
    int z = blockIdx.z;
    const char* pAh = (const char*)Ah;
    const char* pAl = (const char*)Al;
    const char* pBh = (const char*)((z == 0) ? B0h : (z == 1) ? B1h : B2h);
    const char* pBl = (const char*)((z == 0) ? B0l : (z == 1) ? B1l : B2l);
    __half* Ohp = (z == 0) ? O0f : (z == 1) ? O1f : O2f;

    int wm = (wid & 1) * 64;
    int wn = (wid >> 1) * 32;
    int lrow = tid >> 2;
    int lcol = (tid & 3) * 16;

    float acc[4][4][4];
#pragma unroll
    for (int mi = 0; mi < 4; mi++)
#pragma unroll
        for (int ni = 0; ni < 4; ni++)
#pragma unroll
            for (int e = 0; e < 4; e++) acc[mi][ni][e] = 0.0f;

    auto load_chunk = [&](int c, int st) {
        int k0b = c * 64;
#pragma unroll
        for (int half = 0; half < 2; half++) {
            int row = lrow + half * 64;
            unsigned sa = sb + st * STAGE_B + row * 80 + lcol;
            size_t goffA = ((size_t)(m0 + row) * DM) * 2 + k0b + lcol;
            size_t goffB = ((size_t)(n0 + row) * DM) * 2 + k0b + lcol;
            cp16(sa,              pAh + goffA);
            cp16(sa + TILE_B,     pAl + goffA);
            cp16(sa + 2*TILE_B,   pBh + goffB);
            cp16(sa + 3*TILE_B,   pBl + goffB);
        }
    };

    load_chunk(0, 0);
    CP_ASYNC_COMMIT();

    unsigned a_base = (wm + (lane & 15)) * 80 + ((lane >> 4) << 4);
    unsigned b_base = 2*TILE_B + (wn + (lane & 7)) * 80 + (((lane >> 3) & 1) << 4);

    for (int c = 0; c < NCHUNK; c++) {
        if (c + 1 < NCHUNK) {
            load_chunk(c + 1, (c + 1) & 1);
            CP_ASYNC_COMMIT();
            CP_ASYNC_WAIT1();
        } else {
            CP_ASYNC_WAIT0();
        }
        __syncthreads();

        unsigned stb = sb + (c & 1) * STAGE_B;
#pragma unroll
        for (int ks = 0; ks < 2; ks++) {
            unsigned af[4][4], bh[4][2], bl[4][2];
            unsigned ka = stb + ks * 32;
#pragma unroll
            for (int mi = 0; mi < 4; mi++) ldsm4(af[mi], ka + a_base + mi * (16 * 80));
#pragma unroll
            for (int ni = 0; ni < 4; ni++) {
                ldsm2(bh[ni], ka + b_base + ni * (8 * 80));
                ldsm2(bl[ni], ka + b_base + TILE_B + ni * (8 * 80));
            }
#pragma unroll
            for (int mi = 0; mi < 4; mi++)
#pragma unroll
                for (int ni = 0; ni < 4; ni++) mma_bf16(acc[mi][ni], af[mi], bh[ni]);
#pragma unroll
            for (int mi = 0; mi < 4; mi++)
#pragma unroll
                for (int ni = 0; ni < 4; ni++) mma_bf16(acc[mi][ni], af[mi], bl[ni]);
#pragma unroll
            for (int mi = 0; mi < 4; mi++) ldsm4(af[mi], ka + a_base + TILE_B + mi * (16 * 80));
#pragma unroll
            for (int mi = 0; mi < 4; mi++)
#pragma unroll
                for (int ni = 0; ni < 4; ni++) mma_bf16(acc[mi][ni], af[mi], bh[ni]);
        }
        __syncthreads();
    }

    int g = lane >> 2, t = lane & 3;
#pragma unroll
    for (int mi = 0; mi < 4; mi++) {
#pragma unroll
        for (int ni = 0; ni < 4; ni++) {
            int row = m0 + wm + mi * 16 + g;
            int col = n0 + wn + ni * 8 + t * 2;
            if (MODE == 1) {
                float2 v0 = { acc[mi][ni][0], acc[mi][ni][1] };
                float2 v1 = { acc[mi][ni][2], acc[mi][ni][3] };
                *(float2*)(Of + (size_t)row * DM + col)       = v0;
                *(float2*)(Of + (size_t)(row + 8) * DM + col) = v1;
            } else {
#pragma unroll
                for (int rr = 0; rr < 2; rr++) {
                    size_t off = (size_t)(row + rr*8) * DM + col;
                    *(__half2*)(Ohp + off) = __floats2half2_rn(acc[mi][ni][rr*2], acc[mi][ni][rr*2+1]);
                }
            }
        }
    }
}

// ---------------- HMMA flash attention (causal, fp16 interior) ----------------
// CTA: 128 queries x (b,h). 8 warps, warp = 16 query rows x full 64-key block.
// S = Qf*Kf (fp16, 1 term).  PV = Pf*Vf (fp16, 1 term).
#define AQ   128
#define AKB  64
#define QST  144
#define KST  144
#define Q_TILE   (AQ*QST)        // 18432
#define KV_TILE  (AKB*KST)       // 9216
#define KV_STAGE (2*KV_TILE)     // 18432  (K + V)
#define ATTN_SMEM (Q_TILE + 2*KV_STAGE)  // 55296

__global__ __launch_bounds__(256, 2)
void attn_mma()
{
    extern __shared__ __align__(128) char smem[];
    const unsigned sb = smem_u32(smem);
    int tid = threadIdx.x, lane = tid & 31, w = tid >> 5;
    int g = lane >> 2, t = lane & 3;
    int qt = (int)gridDim.x - 1 - (int)blockIdx.x;   // big tiles first
    int h = blockIdx.y, b = blockIdx.z;
    int q0 = qt * AQ;
    const char* pQf = (const char*)g_Qf;
    const char* pKf = (const char*)g_Kf;
    const char* pVf = (const char*)g_Vf;

    // stage Q tile (128 rows x 128B)
#pragma unroll
    for (int i = 0; i < 4; i++) {
        int idx = tid + 256 * i;          // 0..1023
        int row = idx >> 3, c16 = idx & 7;
        size_t off = ((size_t)(b * POS + q0 + row) * DM + h * DH) * 2 + c16 * 16;
        cp16(sb + row * QST + c16 * 16, pQf + off);
    }

    auto load_kv = [&](int kb, int st) {
        int k0 = kb * AKB;
        unsigned base = sb + Q_TILE + st * KV_STAGE;
#pragma unroll
        for (int i = 0; i < 2; i++) {
            int idx = tid + 256 * i;      // 0..511
            int row = idx >> 3, c16 = idx & 7;
            size_t off = ((size_t)(b * POS + k0 + row) * DM + h * DH) * 2 + c16 * 16;
            unsigned d = base + row * KST + c16 * 16;
            cp16(d,           pKf + off);
            cp16(d + KV_TILE, pVf + off);
        }
    };

    load_kv(0, 0);
    CP_ASYNC_COMMIT();

    int nkb = 2 * (qt + 1);
    int qr0 = q0 + 16 * w + g;            // this thread's first query row
    float m0 = -1e30f, m1 = -1e30f, l0 = 0.0f, l1 = 0.0f;
    float o[8][4];
#pragma unroll
    for (int ni = 0; ni < 8; ni++)
#pragma unroll
        for (int e = 0; e < 4; e++) o[ni][e] = 0.0f;

    unsigned qf[4][4];
    unsigned qa = sb + (16 * w + (lane & 15)) * QST + ((lane >> 4) << 4);

    for (int kb = 0; kb < nkb; kb++) {
        if (kb + 1 < nkb) {
            load_kv(kb + 1, (kb + 1) & 1);
            CP_ASYNC_COMMIT();
            CP_ASYNC_WAIT1();
        } else {
            CP_ASYNC_WAIT0();
        }
        __syncthreads();
        if (kb == 0) {                    // Q is resident after first wait
#pragma unroll
            for (int ks = 0; ks < 4; ks++) ldsm4(qf[ks], qa + ks * 32);
        }

        unsigned stg = sb + Q_TILE + (kb & 1) * KV_STAGE;
        int k0 = kb * AKB;
        if (k0 <= q0 + 16 * w + 15) {     // warp has unmasked rows in this block
            // ---- S = Qf * Kf^T (x4-batched K fragments) ----
            float s[8][4];
#pragma unroll
            for (int ni = 0; ni < 8; ni++)
#pragma unroll
                for (int e = 0; e < 4; e++) s[ni][e] = 0.0f;
            unsigned kb4 = stg + ((lane & 7) + ((lane >> 4) << 3)) * KST + (((lane >> 3) & 1) << 4);
#pragma unroll
            for (int ks = 0; ks < 4; ks++)
#pragma unroll
                for (int nip = 0; nip < 4; nip++) {
                    unsigned bf4[4];
                    ldsm4(bf4, kb4 + nip * (16 * KST) + ks * 32);
                    mma_f16(s[2*nip],   qf[ks], bf4);
                    mma_f16(s[2*nip+1], qf[ks], bf4 + 2);
                }
            // ---- scale + causal mask ----
#pragma unroll
            for (int ni = 0; ni < 8; ni++)
#pragma unroll
                for (int e = 0; e < 4; e++) s[ni][e] *= 0.125f;
            if (k0 + 63 > qr0) {
#pragma unroll
                for (int ni = 0; ni < 8; ni++) {
                    int kc = k0 + ni * 8 + t * 2;
                    if (kc     > qr0)     s[ni][0] = -1e30f;
                    if (kc + 1 > qr0)     s[ni][1] = -1e30f;
                    if (kc     > qr0 + 8) s[ni][2] = -1e30f;
                    if (kc + 1 > qr0 + 8) s[ni][3] = -1e30f;
                }
            }
            // ---- online softmax (warp-local, rows g and g+8) ----
            float bm0 = -1e30f, bm1 = -1e30f;
#pragma unroll
            for (int ni = 0; ni < 8; ni++) {
                bm0 = fmaxf(bm0, fmaxf(s[ni][0], s[ni][1]));
                bm1 = fmaxf(bm1, fmaxf(s[ni][2], s[ni][3]));
            }
            bm0 = fmaxf(bm0, __shfl_xor_sync(0xffffffffu, bm0, 1));
            bm0 = fmaxf(bm0, __shfl_xor_sync(0xffffffffu, bm0, 2));
            bm1 = fmaxf(bm1, __shfl_xor_sync(0xffffffffu, bm1, 1));
            bm1 = fmaxf(bm1, __shfl_xor_sync(0xffffffffu, bm1, 2));
            float mn0 = fmaxf(m0, bm0), mn1 = fmaxf(m1, bm1);
            float a0 = __expf(m0 - mn0), a1 = __expf(m1 - mn1);
            m0 = mn0; m1 = mn1;
            float bs0 = 0.0f, bs1 = 0.0f;
#pragma unroll
            for (int ni = 0; ni < 8; ni++) {
                float p0 = __expf(s[ni][0] - m0), p1 = __expf(s[ni][1] - m0);
                float p2 = __expf(s[ni][2] - m1), p3 = __expf(s[ni][3] - m1);
                bs0 += p0 + p1; bs1 += p2 + p3;
                s[ni][0] = p0; s[ni][1] = p1; s[ni][2] = p2; s[ni][3] = p3;
            }
            bs0 += __shfl_xor_sync(0xffffffffu, bs0, 1);
            bs0 += __shfl_xor_sync(0xffffffffu, bs0, 2);
            bs1 += __shfl_xor_sync(0xffffffffu, bs1, 1);
            bs1 += __shfl_xor_sync(0xffffffffu, bs1, 2);
            l0 = l0 * a0 + bs0;
            l1 = l1 * a1 + bs1;
#pragma unroll
            for (int ni = 0; ni < 8; ni++) {
                o[ni][0] *= a0; o[ni][1] *= a0;
                o[ni][2] *= a1; o[ni][3] *= a1;
            }
            // ---- O += Pf * Vf (fp16, x4-batched trans V fragments) ----
            unsigned vb4 = stg + KV_TILE + (lane & 15) * KST + ((lane >> 4) << 4);
#pragma unroll
            for (int ks = 0; ks < 4; ks++) {
                unsigned aP[4] = {
                    pkh(s[2*ks][0],   s[2*ks][1]),
                    pkh(s[2*ks][2],   s[2*ks][3]),
                    pkh(s[2*ks+1][0], s[2*ks+1][1]),
                    pkh(s[2*ks+1][2], s[2*ks+1][3])
                };
#pragma unroll
                for (int nip = 0; nip < 4; nip++) {
                    unsigned bv[4];
                    ldsm4t(bv, vb4 + ks * (16 * KST) + nip * 32);
                    mma_f16(o[2*nip],   aP, bv);
                    mma_f16(o[2*nip+1], aP, bv + 2);
                }
            }
        }
        __syncthreads();
    }

    // ---- finalize: O/l, write bf16 hi/lo concat layout [b,p,h,d] ----
    float inv0 = 1.0f / l0, inv1 = 1.0f / l1;
    size_t r0off = (size_t)(b * POS + qr0) * DM + h * DH;
    size_t r1off = r0off + (size_t)8 * DM;
#pragma unroll
    for (int ni = 0; ni < 8; ni++) {
        int col = ni * 8 + t * 2;
        float vx = o[ni][0] * inv0, vy = o[ni][1] * inv0;
        __nv_bfloat16 hx = __float2bfloat16(vx), hy = __float2bfloat16(vy);
        *(__nv_bfloat162*)(g_Ah + r0off + col) = __halves2bfloat162(hx, hy);
        *(__nv_bfloat162*)(g_Al + r0off + col) = __halves2bfloat162(
            __float2bfloat16(vx - __bfloat162float(hx)),
            __float2bfloat16(vy - __bfloat162float(hy)));
        float wx = o[ni][2] * inv1, wy = o[ni][3] * inv1;
        __nv_bfloat16 gx = __float2bfloat16(wx), gy = __float2bfloat16(wy);
        *(__nv_bfloat162*)(g_Ah + r1off + col) = __halves2bfloat162(gx, gy);
        *(__nv_bfloat162*)(g_Al + r1off + col) = __halves2bfloat162(
            __float2bfloat16(wx - __bfloat162float(gx)),
            __float2bfloat16(wy - __bfloat162float(gy)));
    }
}

// ---------------- launch ----------------
extern "C" void kernel_launch(void* const* d_in, const int* in_sizes, int n_in,
                              void* d_out, int out_size)
{
    (void)in_sizes; (void)n_in; (void)out_size;
    const float* X  = (const float*)d_in[0];
    const float* Wq = (const float*)d_in[1];
    const float* Wk = (const float*)d_in[2];
    const float* Wv = (const float*)d_in[3];
    const float* Wo = (const float*)d_in[4];
    float* out = (float*)d_out;

    __nv_bfloat16 *Xh, *Xl, *Aah, *Aal;
    __half *Qf, *Kf, *Vf;
    __nv_bfloat16 *Wqh, *Wql, *Wkh, *Wkl, *Wvh, *Wvl, *Woh, *Wol;
    cudaGetSymbolAddress((void**)&Xh,  g_Xh);  cudaGetSymbolAddress((void**)&Xl,  g_Xl);
    cudaGetSymbolAddress((void**)&Qf,  g_Qf);
    cudaGetSymbolAddress((void**)&Kf,  g_Kf);
    cudaGetSymbolAddress((void**)&Vf,  g_Vf);
    cudaGetSymbolAddress((void**)&Aah, g_Ah);  cudaGetSymbolAddress((void**)&Aal, g_Al);
    cudaGetSymbolAddress((void**)&Wqh, g_Wqh); cudaGetSymbolAddress((void**)&Wql, g_Wql);
    cudaGetSymbolAddress((void**)&Wkh, g_Wkh); cudaGetSymbolAddress((void**)&Wkl, g_Wkl);
    cudaGetSymbolAddress((void**)&Wvh, g_Wvh); cudaGetSymbolAddress((void**)&Wvl, g_Wvl);
    cudaGetSymbolAddress((void**)&Woh, g_Woh); cudaGetSymbolAddress((void**)&Wol, g_Wol);

    cudaFuncSetAttribute(mma_gemm<0>, cudaFuncAttributeMaxDynamicSharedMemorySize, GEMM_SMEM_BYTES);
    cudaFuncSetAttribute(mma_gemm<1>, cudaFuncAttributeMaxDynamicSharedMemorySize, GEMM_SMEM_BYTES);
    cudaFuncSetAttribute(attn_mma,    cudaFuncAttributeMaxDynamicSharedMemorySize, ATTN_SMEM);

    // 0) precision splits of inputs (weights fused into one launch)
    int n4 = TOK * DM / 4;
    split_f32<<<(n4 + 255) / 256, 256>>>((const float4*)X, (__nv_bfloat162*)Xh, (__nv_bfloat162*)Xl, n4);
    dim3 gw(DM / 32, DM / 32, 4);
    split_w_all<<<gw, 1024>>>(Wq, Wk, Wv, Wo, Wqh, Wql, Wkh, Wkl, Wvh, Wvl, Woh, Wol);

    // 1) fused QKV projection -> single fp16 Q,K,V for attention
    dim3 g1(DM / 128, TOK / 128, 3);
    mma_gemm<0><<<g1, 256, GEMM_SMEM_BYTES>>>(Xh, Xl, Wqh, Wql, Wkh, Wkl, Wvh, Wvl,
                                              nullptr, Qf, Kf, Vf);

    // 2) causal flash attention (fp16 interior) -> bf16 hi/lo A
    dim3 g2(POS / AQ, HEADS, BATCH);
    attn_mma<<<g2, 256, ATTN_SMEM>>>();

    // 3) out projection (split-bf16, 3 terms) -> fp32 output
    dim3 g3(DM / 128, TOK / 128, 1);
    mma_gemm<1><<<g3, 256, GEMM_SMEM_BYTES>>>(Aah, Aal, Woh, Wol, nullptr, nullptr, nullptr, nullptr,
                                              out, nullptr, nullptr, nullptr);
}

// round 15
// speedup vs baseline: 2.1315x; 1.8672x over previous
#include <cuda_runtime.h>
#include <cuda_fp16.h>

#define DM   1024
#define HEADS 16
#define DH    64
#define POS  2048
#define BATCH 2
#define TOK  (BATCH*POS)   // 4096

// ---------------- scratch (device globals: allocation-free) ----------------
__device__ __half g_Xf[TOK*DM];
__device__ __half g_Qf[TOK*DM], g_Kf[TOK*DM], g_Vf[TOK*DM];
__device__ __half g_Af[TOK*DM];
__device__ __half g_Wqf[DM*DM], g_Wkf[DM*DM], g_Wvf[DM*DM], g_Wof[DM*DM];

// ---------------- helpers ----------------
__device__ __forceinline__ unsigned smem_u32(const void* p) {
    unsigned r;
    asm("{ .reg .u64 t; cvta.to.shared.u64 t, %1; cvt.u32.u64 %0, t; }" : "=r"(r) : "l"(p));
    return r;
}
__device__ __forceinline__ void cp16(unsigned s, const void* g) {
    asm volatile("cp.async.cg.shared.global [%0], [%1], 16;" :: "r"(s), "l"(g) : "memory");
}
#define CP_ASYNC_COMMIT() asm volatile("cp.async.commit_group;" ::: "memory")
#define CP_ASYNC_WAIT1()  asm volatile("cp.async.wait_group 1;" ::: "memory")
#define CP_ASYNC_WAIT0()  asm volatile("cp.async.wait_group 0;" ::: "memory")

__device__ __forceinline__ void ldsm4(unsigned* r, unsigned a) {
    asm volatile("ldmatrix.sync.aligned.m8n8.x4.shared.b16 {%0,%1,%2,%3}, [%4];"
        : "=r"(r[0]), "=r"(r[1]), "=r"(r[2]), "=r"(r[3]) : "r"(a));
}
__device__ __forceinline__ void ldsm2(unsigned* r, unsigned a) {
    asm volatile("ldmatrix.sync.aligned.m8n8.x2.shared.b16 {%0,%1}, [%2];"
        : "=r"(r[0]), "=r"(r[1]) : "r"(a));
}
__device__ __forceinline__ void ldsm4t(unsigned* r, unsigned a) {
    asm volatile("ldmatrix.sync.aligned.m8n8.x4.trans.shared.b16 {%0,%1,%2,%3}, [%4];"
        : "=r"(r[0]), "=r"(r[1]), "=r"(r[2]), "=r"(r[3]) : "r"(a));
}
__device__ __forceinline__ void mma_f16(float* d, const unsigned* a, const unsigned* b) {
    asm volatile("mma.sync.aligned.m16n8k16.row.col.f32.f16.f16.f32 "
        "{%0,%1,%2,%3}, {%4,%5,%6,%7}, {%8,%9}, {%0,%1,%2,%3};"
        : "+f"(d[0]), "+f"(d[1]), "+f"(d[2]), "+f"(d[3])
        : "r"(a[0]), "r"(a[1]), "r"(a[2]), "r"(a[3]), "r"(b[0]), "r"(b[1]));
}
__device__ __forceinline__ unsigned pkh(float a, float b) {
    __half2 t = __floats2half2_rn(a, b);
    return *(unsigned*)&t;
}

// ---------------- fp32 -> fp16 conversion kernels ----------------
__global__ void cvt_x(const float4* __restrict__ src, __half2* __restrict__ dst, int n4)
{
    int i = blockIdx.x * blockDim.x + threadIdx.x;
    if (i >= n4) return;
    float4 v = src[i];
    dst[i*2+0] = __floats2half2_rn(v.x, v.y);
    dst[i*2+1] = __floats2half2_rn(v.z, v.w);
}

// Fused weight transpose+convert (all 4 matrices in one launch, z selects).
// z<3 (QKV layout): src (k,n) = W[n>>6][k][n&63].  z=3 (out): src (k,n) = W[k*DM+n].
// Output: Wt[n][k] fp16.
__global__ __launch_bounds__(1024)
void cvt_w_all(const float* __restrict__ Wq, const float* __restrict__ Wk,
               const float* __restrict__ Wv, const float* __restrict__ Wo,
               __half* __restrict__ Fq, __half* __restrict__ Fk,
               __half* __restrict__ Fv, __half* __restrict__ Fo)
{
    __shared__ float tile[32][33];
    int z = blockIdx.z;
    const float* W = (z == 0) ? Wq : (z == 1) ? Wk : (z == 2) ? Wv : Wo;
    __half* f = (z == 0) ? Fq : (z == 1) ? Fk : (z == 2) ? Fv : Fo;
    int n0 = blockIdx.x * 32, k0 = blockIdx.y * 32;
    int tx = threadIdx.x & 31, ty = threadIdx.x >> 5;
    {
        int n = n0 + tx, k = k0 + ty;
        float x = (z < 3) ? W[(size_t)(n >> 6) * (DM * DH) + (size_t)k * DH + (n & 63)]
                          : W[(size_t)k * DM + n];
        tile[ty][tx] = x;
    }
    __syncthreads();
    {
        int n = n0 + ty, k = k0 + tx;
        f[(size_t)n * DM + k] = __float2half(tile[tx][ty]);
    }
}

// ---------------- fp16 HMMA GEMM: O[4096x1024] = A x B^T ----------------
// A: [4096][1024] fp16.  B: [1024 n][1024 k] fp16.  Single term, fp32 accumulate.
// CTA tile 128x128, 8 warps (warp tile 64x32), K-chunk 64 fp16 (128B) x 16 chunks,
// double-buffered cp.async. Row stride 144B (16r mod 128 distinct -> ldsm conflict-free).
// MODE 0: epilogue fp16 (Q/K/V). MODE 1: fp32 (final output).
#define TILE_B   18432      // 128 rows x 144B
#define STAGE_B  36864      // A tile + B tile
#define NCHUNK   16
#define GEMM_SMEM_BYTES (2*STAGE_B)  // 73728

template<int MODE>
__global__ __launch_bounds__(256, 2)
void mma_gemm(const __half* __restrict__ A,
              const __half* __restrict__ B0, const __half* __restrict__ B1,
              const __half* __restrict__ B2,
              float* __restrict__ Of,
              __half* O0, __half* O1, __half* O2)
{
    extern __shared__ __align__(128) char smem[];
    const unsigned sb = smem_u32(smem);
    int tid = threadIdx.x, lane = tid & 31, wid = tid >> 5;
    int n0 = blockIdx.x * 128, m0 = blockIdx.y * 128;
    int z = blockIdx.z;
    const char* pA = (const char*)A;
    const char* pB = (const char*)((z == 0) ? B0 : (z == 1) ? B1 : B2);
    __half* Oh = (z == 0) ? O0 : (z == 1) ? O1 : O2;

    int wm = (wid & 1) * 64;
    int wn = (wid >> 1) * 32;
    int lr = tid >> 3;            // 0..31
    int lc = (tid & 7) * 16;      // byte col in 128B chunk row

    float acc[4][4][4];
#pragma unroll
    for (int mi = 0; mi < 4; mi++)
#pragma unroll
        for (int ni = 0; ni < 4; ni++)
#pragma unroll
            for (int e = 0; e < 4; e++) acc[mi][ni][e] = 0.0f;

    auto load_chunk = [&](int c, int st) {
        int k0b = c * 128;   // 64 fp16 = 128B per chunk; 16 chunks cover K=1024
#pragma unroll
        for (int q = 0; q < 4; q++) {
            int row = lr + q * 32;
            unsigned sa = sb + st * STAGE_B + row * 144 + lc;
            size_t goffA = ((size_t)(m0 + row) * DM) * 2 + k0b + lc;
            size_t goffB = ((size_t)(n0 + row) * DM) * 2 + k0b + lc;
            cp16(sa,          pA + goffA);
            cp16(sa + TILE_B, pB + goffB);
        }
    };

    load_chunk(0, 0);
    CP_ASYNC_COMMIT();

    unsigned a_base = (wm + (lane & 15)) * 144 + ((lane >> 4) << 4);
    unsigned b_base = TILE_B + (wn + (lane & 7)) * 144 + (((lane >> 3) & 1) << 4);

    for (int c = 0; c < NCHUNK; c++) {
        if (c + 1 < NCHUNK) {
            load_chunk(c + 1, (c + 1) & 1);
            CP_ASYNC_COMMIT();
            CP_ASYNC_WAIT1();
        } else {
            CP_ASYNC_WAIT0();
        }
        __syncthreads();

        unsigned stb = sb + (c & 1) * STAGE_B;
#pragma unroll
        for (int ks = 0; ks < 4; ks++) {
            unsigned af[4][4], bf[4][2];
            unsigned ka = stb + ks * 32;
#pragma unroll
            for (int mi = 0; mi < 4; mi++) ldsm4(af[mi], ka + a_base + mi * (16 * 144));
#pragma unroll
            for (int ni = 0; ni < 4; ni++) ldsm2(bf[ni], ka + b_base + ni * (8 * 144));
#pragma unroll
            for (int mi = 0; mi < 4; mi++)
#pragma unroll
                for (int ni = 0; ni < 4; ni++) mma_f16(acc[mi][ni], af[mi], bf[ni]);
        }
        __syncthreads();
    }

    int g = lane >> 2, t = lane & 3;
#pragma unroll
    for (int mi = 0; mi < 4; mi++) {
#pragma unroll
        for (int ni = 0; ni < 4; ni++) {
            int row = m0 + wm + mi * 16 + g;
            int col = n0 + wn + ni * 8 + t * 2;
            if (MODE == 1) {
                float2 v0 = { acc[mi][ni][0], acc[mi][ni][1] };
                float2 v1 = { acc[mi][ni][2], acc[mi][ni][3] };
                *(float2*)(Of + (size_t)row * DM + col)       = v0;
                *(float2*)(Of + (size_t)(row + 8) * DM + col) = v1;
            } else {
                *(__half2*)(Oh + (size_t)row * DM + col) =
                    __floats2half2_rn(acc[mi][ni][0], acc[mi][ni][1]);
                *(__half2*)(Oh + (size_t)(row + 8) * DM + col) =
                    __floats2half2_rn(acc[mi][ni][2], acc[mi][ni][3]);
            }
        }
    }
}

// ---------------- HMMA flash attention (causal, fp16 interior) ----------------
// CTA: 128 queries x (b,h). 8 warps, warp = 16 query rows x full 64-key block.
// S = Qf*Kf.  PV = Pf*Vf.  Epilogue writes single fp16 A.
#define AQ   128
#define AKB  64
#define QST  144
#define KST  144
#define Q_TILE   (AQ*QST)        // 18432
#define KV_TILE  (AKB*KST)       // 9216
#define KV_STAGE (2*KV_TILE)     // 18432  (K + V)
#define ATTN_SMEM (Q_TILE + 2*KV_STAGE)  // 55296

__global__ __launch_bounds__(256, 2)
void attn_mma()
{
    extern __shared__ __align__(128) char smem[];
    const unsigned sb = smem_u32(smem);
    int tid = threadIdx.x, lane = tid & 31, w = tid >> 5;
    int g = lane >> 2, t = lane & 3;
    int qt = (int)gridDim.x - 1 - (int)blockIdx.x;   // big tiles first
    int h = blockIdx.y, b = blockIdx.z;
    int q0 = qt * AQ;
    const char* pQf = (const char*)g_Qf;
    const char* pKf = (const char*)g_Kf;
    const char* pVf = (const char*)g_Vf;

    // stage Q tile (128 rows x 128B)
#pragma unroll
    for (int i = 0; i < 4; i++) {
        int idx = tid + 256 * i;          // 0..1023
        int row = idx >> 3, c16 = idx & 7;
        size_t off = ((size_t)(b * POS + q0 + row) * DM + h * DH) * 2 + c16 * 16;
        cp16(sb + row * QST + c16 * 16, pQf + off);
    }

    auto load_kv = [&](int kb, int st) {
        int k0 = kb * AKB;
        unsigned base = sb + Q_TILE + st * KV_STAGE;
#pragma unroll
        for (int i = 0; i < 2; i++) {
            int idx = tid + 256 * i;      // 0..511
            int row = idx >> 3, c16 = idx & 7;
            size_t off = ((size_t)(b * POS + k0 + row) * DM + h * DH) * 2 + c16 * 16;
            unsigned d = base + row * KST + c16 * 16;
            cp16(d,           pKf + off);
            cp16(d + KV_TILE, pVf + off);
        }
    };

    load_kv(0, 0);
    CP_ASYNC_COMMIT();

    int nkb = 2 * (qt + 1);
    int qr0 = q0 + 16 * w + g;            // this thread's first query row
    float m0 = -1e30f, m1 = -1e30f, l0 = 0.0f, l1 = 0.0f;
    float o[8][4];
#pragma unroll
    for (int ni = 0; ni < 8; ni++)
#pragma unroll
        for (int e = 0; e < 4; e++) o[ni][e] = 0.0f;

    unsigned qf[4][4];
    unsigned qa = sb + (16 * w + (lane & 15)) * QST + ((lane >> 4) << 4);

    for (int kb = 0; kb < nkb; kb++) {
        if (kb + 1 < nkb) {
            load_kv(kb + 1, (kb + 1) & 1);
            CP_ASYNC_COMMIT();
            CP_ASYNC_WAIT1();
        } else {
            CP_ASYNC_WAIT0();
        }
        __syncthreads();
        if (kb == 0) {                    // Q is resident after first wait
#pragma unroll
            for (int ks = 0; ks < 4; ks++) ldsm4(qf[ks], qa + ks * 32);
        }

        unsigned stg = sb + Q_TILE + (kb & 1) * KV_STAGE;
        int k0 = kb * AKB;
        if (k0 <= q0 + 16 * w + 15) {     // warp has unmasked rows in this block
            // ---- S = Qf * Kf^T (x4-batched K fragments) ----
            float s[8][4];
#pragma unroll
            for (int ni = 0; ni < 8; ni++)
#pragma unroll
                for (int e = 0; e < 4; e++) s[ni][e] = 0.0f;
            unsigned kb4 = stg + ((lane & 7) + ((lane >> 4) << 3)) * KST + (((lane >> 3) & 1) << 4);
#pragma unroll
            for (int ks = 0; ks < 4; ks++)
#pragma unroll
                for (int nip = 0; nip < 4; nip++) {
                    unsigned bf4[4];
                    ldsm4(bf4, kb4 + nip * (16 * KST) + ks * 32);
                    mma_f16(s[2*nip],   qf[ks], bf4);
                    mma_f16(s[2*nip+1], qf[ks], bf4 + 2);
                }
            // ---- scale + causal mask ----
#pragma unroll
            for (int ni = 0; ni < 8; ni++)
#pragma unroll
                for (int e = 0; e < 4; e++) s[ni][e] *= 0.125f;
            if (k0 + 63 > qr0) {
#pragma unroll
                for (int ni = 0; ni < 8; ni++) {
                    int kc = k0 + ni * 8 + t * 2;
                    if (kc     > qr0)     s[ni][0] = -1e30f;
                    if (kc + 1 > qr0)     s[ni][1] = -1e30f;
                    if (kc     > qr0 + 8) s[ni][2] = -1e30f;
                    if (kc + 1 > qr0 + 8) s[ni][3] = -1e30f;
                }
            }
            // ---- online softmax (warp-local, rows g and g+8) ----
            float bm0 = -1e30f, bm1 = -1e30f;
#pragma unroll
            for (int ni = 0; ni < 8; ni++) {
                bm0 = fmaxf(bm0, fmaxf(s[ni][0], s[ni][1]));
                bm1 = fmaxf(bm1, fmaxf(s[ni][2], s[ni][3]));
            }
            bm0 = fmaxf(bm0, __shfl_xor_sync(0xffffffffu, bm0, 1));
            bm0 = fmaxf(bm0, __shfl_xor_sync(0xffffffffu, bm0, 2));
            bm1 = fmaxf(bm1, __shfl_xor_sync(0xffffffffu, bm1, 1));
            bm1 = fmaxf(bm1, __shfl_xor_sync(0xffffffffu, bm1, 2));
            float mn0 = fmaxf(m0, bm0), mn1 = fmaxf(m1, bm1);
            float a0 = __expf(m0 - mn0), a1 = __expf(m1 - mn1);
            m0 = mn0; m1 = mn1;
            float bs0 = 0.0f, bs1 = 0.0f;
#pragma unroll
            for (int ni = 0; ni < 8; ni++) {
                float p0 = __expf(s[ni][0] - m0), p1 = __expf(s[ni][1] - m0);
                float p2 = __expf(s[ni][2] - m1), p3 = __expf(s[ni][3] - m1);
                bs0 += p0 + p1; bs1 += p2 + p3;
                s[ni][0] = p0; s[ni][1] = p1; s[ni][2] = p2; s[ni][3] = p3;
            }
            bs0 += __shfl_xor_sync(0xffffffffu, bs0, 1);
            bs0 += __shfl_xor_sync(0xffffffffu, bs0, 2);
            bs1 += __shfl_xor_sync(0xffffffffu, bs1, 1);
            bs1 += __shfl_xor_sync(0xffffffffu, bs1, 2);
            l0 = l0 * a0 + bs0;
            l1 = l1 * a1 + bs1;
#pragma unroll
            for (int ni = 0; ni < 8; ni++) {
                o[ni][0] *= a0; o[ni][1] *= a0;
                o[ni][2] *= a1; o[ni][3] *= a1;
            }
            // ---- O += Pf * Vf (x4-batched trans V fragments) ----
            unsigned vb4 = stg + KV_TILE + (lane & 15) * KST + ((lane >> 4) << 4);
#pragma unroll
            for (int ks = 0; ks < 4; ks++) {
                unsigned aP[4] = {
                    pkh(s[2*ks][0],   s[2*ks][1]),
                    pkh(s[2*ks][2],   s[2*ks][3]),
                    pkh(s[2*ks+1][0], s[2*ks+1][1]),
                    pkh(s[2*ks+1][2], s[2*ks+1][3])
                };
#pragma unroll
                for (int nip = 0; nip < 4; nip++) {
                    unsigned bv[4];
                    ldsm4t(bv, vb4 + ks * (16 * KST) + nip * 32);
                    mma_f16(o[2*nip],   aP, bv);
                    mma_f16(o[2*nip+1], aP, bv + 2);
                }
            }
        }
        __syncthreads();
    }

    // ---- finalize: O/l, write single fp16 concat layout [b,p,h,d] ----
    float inv0 = 1.0f / l0, inv1 = 1.0f / l1;
    size_t r0off = (size_t)(b * POS + qr0) * DM + h * DH;
    size_t r1off = r0off + (size_t)8 * DM;
#pragma unroll
    for (int ni = 0; ni < 8; ni++) {
        int col = ni * 8 + t * 2;
        *(__half2*)(g_Af + r0off + col) = __floats2half2_rn(o[ni][0] * inv0, o[ni][1] * inv0);
        *(__half2*)(g_Af + r1off + col) = __floats2half2_rn(o[ni][2] * inv1, o[ni][3] * inv1);
    }
}

// ---------------- launch ----------------
extern "C" void kernel_launch(void* const* d_in, const int* in_sizes, int n_in,
                              void* d_out, int out_size)
{
    (void)in_sizes; (void)n_in; (void)out_size;
    const float* X  = (const float*)d_in[0];
    const float* Wq = (const float*)d_in[1];
    const float* Wk = (const float*)d_in[2];
    const float* Wv = (const float*)d_in[3];
    const float* Wo = (const float*)d_in[4];
    float* out = (float*)d_out;

    __half *Xf, *Qf, *Kf, *Vf, *Af, *Wqf, *Wkf, *Wvf, *Wof;
    cudaGetSymbolAddress((void**)&Xf,  g_Xf);
    cudaGetSymbolAddress((void**)&Qf,  g_Qf);
    cudaGetSymbolAddress((void**)&Kf,  g_Kf);
    cudaGetSymbolAddress((void**)&Vf,  g_Vf);
    cudaGetSymbolAddress((void**)&Af,  g_Af);
    cudaGetSymbolAddress((void**)&Wqf, g_Wqf);
    cudaGetSymbolAddress((void**)&Wkf, g_Wkf);
    cudaGetSymbolAddress((void**)&Wvf, g_Wvf);
    cudaGetSymbolAddress((void**)&Wof, g_Wof);

    cudaFuncSetAttribute(mma_gemm<0>, cudaFuncAttributeMaxDynamicSharedMemorySize, GEMM_SMEM_BYTES);
    cudaFuncSetAttribute(mma_gemm<1>, cudaFuncAttributeMaxDynamicSharedMemorySize, GEMM_SMEM_BYTES);
    cudaFuncSetAttribute(attn_mma,    cudaFuncAttributeMaxDynamicSharedMemorySize, ATTN_SMEM);

    // 0) fp16 conversions
    int n4 = TOK * DM / 4;
    cvt_x<<<(n4 + 255) / 256, 256>>>((const float4*)X, (__half2*)Xf, n4);
    dim3 gw(DM / 32, DM / 32, 4);
    cvt_w_all<<<gw, 1024>>>(Wq, Wk, Wv, Wo, Wqf, Wkf, Wvf, Wof);

    // 1) fused QKV projection (fp16 single-term) -> fp16 Q,K,V
    dim3 g1(DM / 128, TOK / 128, 3);
    mma_gemm<0><<<g1, 256, GEMM_SMEM_BYTES>>>(Xf, Wqf, Wkf, Wvf, nullptr, Qf, Kf, Vf);

    // 2) causal flash attention (fp16 interior) -> fp16 A
    dim3 g2(POS / AQ, HEADS, BATCH);
    attn_mma<<<g2, 256, ATTN_SMEM>>>();

    // 3) out projection (fp16 single-term) -> fp32 output
    dim3 g3(DM / 128, TOK / 128, 1);
    mma_gemm<1><<<g3, 256, GEMM_SMEM_BYTES>>>(Af, Wof, nullptr, nullptr, out, nullptr, nullptr, nullptr);
}

// round 16
// speedup vs baseline: 2.2087x; 1.0362x over previous
#include <cuda_runtime.h>
#include <cuda_fp16.h>

#define DM   1024
#define HEADS 16
#define DH    64
#define POS  2048
#define BATCH 2
#define TOK  (BATCH*POS)   // 4096

// ---------------- scratch (device globals: allocation-free) ----------------
__device__ __half g_Xf[TOK*DM];
__device__ __half g_Qf[TOK*DM], g_Kf[TOK*DM], g_Vf[TOK*DM];
__device__ __half g_Af[TOK*DM];
__device__ __half g_Wqf[DM*DM], g_Wkf[DM*DM], g_Wvf[DM*DM], g_Wof[DM*DM];

// Q pre-scale: 1/sqrt(64) * log2(e)  -> attention scores land in log2 domain
#define QSCALE 0.180336879f

// ---------------- helpers ----------------
__device__ __forceinline__ unsigned smem_u32(const void* p) {
    unsigned r;
    asm("{ .reg .u64 t; cvta.to.shared.u64 t, %1; cvt.u32.u64 %0, t; }" : "=r"(r) : "l"(p));
    return r;
}
__device__ __forceinline__ void cp16(unsigned s, const void* g) {
    asm volatile("cp.async.cg.shared.global [%0], [%1], 16;" :: "r"(s), "l"(g) : "memory");
}
#define CP_ASYNC_COMMIT() asm volatile("cp.async.commit_group;" ::: "memory")
#define CP_ASYNC_WAIT1()  asm volatile("cp.async.wait_group 1;" ::: "memory")
#define CP_ASYNC_WAIT0()  asm volatile("cp.async.wait_group 0;" ::: "memory")

__device__ __forceinline__ void ldsm4(unsigned* r, unsigned a) {
    asm volatile("ldmatrix.sync.aligned.m8n8.x4.shared.b16 {%0,%1,%2,%3}, [%4];"
        : "=r"(r[0]), "=r"(r[1]), "=r"(r[2]), "=r"(r[3]) : "r"(a));
}
__device__ __forceinline__ void ldsm2(unsigned* r, unsigned a) {
    asm volatile("ldmatrix.sync.aligned.m8n8.x2.shared.b16 {%0,%1}, [%2];"
        : "=r"(r[0]), "=r"(r[1]) : "r"(a));
}
__device__ __forceinline__ void ldsm2t(unsigned* r, unsigned a) {
    asm volatile("ldmatrix.sync.aligned.m8n8.x2.trans.shared.b16 {%0,%1}, [%2];"
        : "=r"(r[0]), "=r"(r[1]) : "r"(a));
}
__device__ __forceinline__ void ldsm4t(unsigned* r, unsigned a) {
    asm volatile("ldmatrix.sync.aligned.m8n8.x4.trans.shared.b16 {%0,%1,%2,%3}, [%4];"
        : "=r"(r[0]), "=r"(r[1]), "=r"(r[2]), "=r"(r[3]) : "r"(a));
}
__device__ __forceinline__ void mma_f16(float* d, const unsigned* a, const unsigned* b) {
    asm volatile("mma.sync.aligned.m16n8k16.row.col.f32.f16.f16.f32 "
        "{%0,%1,%2,%3}, {%4,%5,%6,%7}, {%8,%9}, {%0,%1,%2,%3};"
        : "+f"(d[0]), "+f"(d[1]), "+f"(d[2]), "+f"(d[3])
        : "r"(a[0]), "r"(a[1]), "r"(a[2]), "r"(a[3]), "r"(b[0]), "r"(b[1]));
}
// pack two floats to half2, then 2^x on both halves in one MUFU op
__device__ __forceinline__ unsigned h2ex2(float a, float b) {
    __half2 t = __floats2half2_rn(a, b);
    unsigned u = *(unsigned*)&t;
    asm("ex2.approx.f16x2 %0, %0;" : "+r"(u));
    return u;
}
__device__ __forceinline__ float ex2f(float x) {
    float r; asm("ex2.approx.f32 %0, %1;" : "=f"(r) : "f"(x)); return r;
}

// ---------------- fp32 -> fp16 conversion kernels ----------------
__global__ void cvt_x(const float4* __restrict__ src, __half2* __restrict__ dst, int n4)
{
    int i = blockIdx.x * blockDim.x + threadIdx.x;
    if (i >= n4) return;
    float4 v = src[i];
    dst[i*2+0] = __floats2half2_rn(v.x, v.y);
    dst[i*2+1] = __floats2half2_rn(v.z, v.w);
}

// Fused weight transpose+convert (all 4 matrices in one launch, z selects).
__global__ __launch_bounds__(1024)
void cvt_w_all(const float* __restrict__ Wq, const float* __restrict__ Wk,
               const float* __restrict__ Wv, const float* __restrict__ Wo,
               __half* __restrict__ Fq, __half* __restrict__ Fk,
               __half* __restrict__ Fv, __half* __restrict__ Fo)
{
    __shared__ float tile[32][33];
    int z = blockIdx.z;
    const float* W = (z == 0) ? Wq : (z == 1) ? Wk : (z == 2) ? Wv : Wo;
    __half* f = (z == 0) ? Fq : (z == 1) ? Fk : (z == 2) ? Fv : Fo;
    int n0 = blockIdx.x * 32, k0 = blockIdx.y * 32;
    int tx = threadIdx.x & 31, ty = threadIdx.x >> 5;
    {
        int n = n0 + tx, k = k0 + ty;
        float x = (z < 3) ? W[(size_t)(n >> 6) * (DM * DH) + (size_t)k * DH + (n & 63)]
                          : W[(size_t)k * DM + n];
        tile[ty][tx] = x;
    }
    __syncthreads();
    {
        int n = n0 + ty, k = k0 + tx;
        f[(size_t)n * DM + k] = __float2half(tile[tx][ty]);
    }
}

// ---------------- fp16 HMMA GEMM: O[4096x1024] = A x B^T ----------------
// MODE 0: epilogue fp16 (Q/K/V; z==0 output pre-scaled by QSCALE). MODE 1: fp32.
#define TILE_B   18432      // 128 rows x 144B
#define STAGE_B  36864
#define NCHUNK   16
#define GEMM_SMEM_BYTES (2*STAGE_B)  // 73728

template<int MODE>
__global__ __launch_bounds__(256, 2)
void mma_gemm(const __half* __restrict__ A,
              const __half* __restrict__ B0, const __half* __restrict__ B1,
              const __half* __restrict__ B2,
              float* __restrict__ Of,
              __half* O0, __half* O1, __half* O2)
{
    extern __shared__ __align__(128) char smem[];
    const unsigned sb = smem_u32(smem);
    int tid = threadIdx.x, lane = tid & 31, wid = tid >> 5;
    int n0 = blockIdx.x * 128, m0 = blockIdx.y * 128;
    int z = blockIdx.z;
    const char* pA = (const char*)A;
    const char* pB = (const char*)((z == 0) ? B0 : (z == 1) ? B1 : B2);
    __half* Oh = (z == 0) ? O0 : (z == 1) ? O1 : O2;

    int wm = (wid & 1) * 64;
    int wn = (wid >> 1) * 32;
    int lr = tid >> 3;
    int lc = (tid & 7) * 16;

    float acc[4][4][4];
#pragma unroll
    for (int mi = 0; mi < 4; mi++)
#pragma unroll
        for (int ni = 0; ni < 4; ni++)
#pragma unroll
            for (int e = 0; e < 4; e++) acc[mi][ni][e] = 0.0f;

    auto load_chunk = [&](int c, int st) {
        int k0b = c * 128;
#pragma unroll
        for (int q = 0; q < 4; q++) {
            int row = lr + q * 32;
            unsigned sa = sb + st * STAGE_B + row * 144 + lc;
            size_t goffA = ((size_t)(m0 + row) * DM) * 2 + k0b + lc;
            size_t goffB = ((size_t)(n0 + row) * DM) * 2 + k0b + lc;
            cp16(sa,          pA + goffA);
            cp16(sa + TILE_B, pB + goffB);
        }
    };

    load_chunk(0, 0);
    CP_ASYNC_COMMIT();

    unsigned a_base = (wm + (lane & 15)) * 144 + ((lane >> 4) << 4);
    unsigned b_base = TILE_B + (wn + (lane & 7)) * 144 + (((lane >> 3) & 1) << 4);

    for (int c = 0; c < NCHUNK; c++) {
        if (c + 1 < NCHUNK) {
            load_chunk(c + 1, (c + 1) & 1);
            CP_ASYNC_COMMIT();
            CP_ASYNC_WAIT1();
        } else {
            CP_ASYNC_WAIT0();
        }
        __syncthreads();

        unsigned stb = sb + (c & 1) * STAGE_B;
#pragma unroll
        for (int ks = 0; ks < 4; ks++) {
            unsigned af[4][4], bf[4][2];
            unsigned ka = stb + ks * 32;
#pragma unroll
            for (int mi = 0; mi < 4; mi++) ldsm4(af[mi], ka + a_base + mi * (16 * 144));
#pragma unroll
            for (int ni = 0; ni < 4; ni++) ldsm2(bf[ni], ka + b_base + ni * (8 * 144));
#pragma unroll
            for (int mi = 0; mi < 4; mi++)
#pragma unroll
                for (int ni = 0; ni < 4; ni++) mma_f16(acc[mi][ni], af[mi], bf[ni]);
        }
        __syncthreads();
    }

    int g = lane >> 2, t = lane & 3;
    float sc = (MODE == 0 && z == 0) ? QSCALE : 1.0f;
#pragma unroll
    for (int mi = 0; mi < 4; mi++) {
#pragma unroll
        for (int ni = 0; ni < 4; ni++) {
            int row = m0 + wm + mi * 16 + g;
            int col = n0 + wn + ni * 8 + t * 2;
            if (MODE == 1) {
                float2 v0 = { acc[mi][ni][0], acc[mi][ni][1] };
                float2 v1 = { acc[mi][ni][2], acc[mi][ni][3] };
                *(float2*)(Of + (size_t)row * DM + col)       = v0;
                *(float2*)(Of + (size_t)(row + 8) * DM + col) = v1;
            } else {
                *(__half2*)(Oh + (size_t)row * DM + col) =
                    __floats2half2_rn(acc[mi][ni][0] * sc, acc[mi][ni][1] * sc);
                *(__half2*)(Oh + (size_t)(row + 8) * DM + col) =
                    __floats2half2_rn(acc[mi][ni][2] * sc, acc[mi][ni][3] * sc);
            }
        }
    }
}

// ---------------- HMMA flash attention (causal, fp16, log2-domain softmax) ----------------
// CTA: 128 queries x (b,h). 8 warps, warp = 16 query rows x full 64-key block.
// Q pre-scaled by 0.125*log2e -> S is log2-domain; P = ex2.f16x2(S - m).
// l accumulated by an extra HMMA against a constant ones-column in the V row pad.
#define AQ   128
#define AKB  64
#define QST  144
#define KST  144
#define Q_TILE   (AQ*QST)        // 18432
#define KV_TILE  (AKB*KST)       // 9216
#define KV_STAGE (2*KV_TILE)     // 18432  (K + V)
#define ATTN_SMEM (Q_TILE + 2*KV_STAGE)  // 55296

__global__ __launch_bounds__(256, 2)
void attn_mma()
{
    extern __shared__ __align__(128) char smem[];
    const unsigned sb = smem_u32(smem);
    int tid = threadIdx.x, lane = tid & 31, w = tid >> 5;
    int g = lane >> 2, t = lane & 3;
    int qt = (int)gridDim.x - 1 - (int)blockIdx.x;   // big tiles first
    int h = blockIdx.y, b = blockIdx.z;
    int q0 = qt * AQ;
    const char* pQf = (const char*)g_Qf;
    const char* pKf = (const char*)g_Kf;
    const char* pVf = (const char*)g_Vf;

    // ones-column pattern in the V row pad (bytes 128..143 of each V row, both stages)
    if (tid < 128) {
        int st = tid >> 6, row = tid & 63;
        *(uint4*)(smem + Q_TILE + st * KV_STAGE + KV_TILE + row * KST + 128) =
            make_uint4(0x00003C00u, 0u, 0u, 0u);   // fp16 1.0 at col 64, zeros elsewhere
    }

    // stage Q tile (128 rows x 128B)
#pragma unroll
    for (int i = 0; i < 4; i++) {
        int idx = tid + 256 * i;
        int row = idx >> 3, c16 = idx & 7;
        size_t off = ((size_t)(b * POS + q0 + row) * DM + h * DH) * 2 + c16 * 16;
        cp16(sb + row * QST + c16 * 16, pQf + off);
    }

    auto load_kv = [&](int kb, int st) {
        int k0 = kb * AKB;
        unsigned base = sb + Q_TILE + st * KV_STAGE;
#pragma unroll
        for (int i = 0; i < 2; i++) {
            int idx = tid + 256 * i;
            int row = idx >> 3, c16 = idx & 7;
            size_t off = ((size_t)(b * POS + k0 + row) * DM + h * DH) * 2 + c16 * 16;
            unsigned d = base + row * KST + c16 * 16;
            cp16(d,           pKf + off);
            cp16(d + KV_TILE, pVf + off);
        }
    };

    load_kv(0, 0);
    CP_ASYNC_COMMIT();

    int nkb = 2 * (qt + 1);
    int qr0 = q0 + 16 * w + g;
    float m0 = -1e30f, m1 = -1e30f;
    float o[8][4];
    float oc[4] = {0.0f, 0.0f, 0.0f, 0.0f};   // ones-column accumulator (l lives at t=0)
#pragma unroll
    for (int ni = 0; ni < 8; ni++)
#pragma unroll
        for (int e = 0; e < 4; e++) o[ni][e] = 0.0f;

    unsigned qf[4][4];
    unsigned bones[2];
    unsigned qa = sb + (16 * w + (lane & 15)) * QST + ((lane >> 4) << 4);

    for (int kb = 0; kb < nkb; kb++) {
        if (kb + 1 < nkb) {
            load_kv(kb + 1, (kb + 1) & 1);
            CP_ASYNC_COMMIT();
            CP_ASYNC_WAIT1();
        } else {
            CP_ASYNC_WAIT0();
        }
        __syncthreads();
        if (kb == 0) {
#pragma unroll
            for (int ks = 0; ks < 4; ks++) ldsm4(qf[ks], qa + ks * 32);
            // constant ones-column B fragment (same for every ks/kb) - load once
            ldsm2t(bones, sb + Q_TILE + KV_TILE + (lane & 15) * KST + 128);
        }

        unsigned stg = sb + Q_TILE + (kb & 1) * KV_STAGE;
        int k0 = kb * AKB;
        if (k0 <= q0 + 16 * w + 15) {
            // ---- S = Qf * Kf^T (log2 domain; scale pre-folded into Q) ----
            float s[8][4];
#pragma unroll
            for (int ni = 0; ni < 8; ni++)
#pragma unroll
                for (int e = 0; e < 4; e++) s[ni][e] = 0.0f;
            unsigned kb4 = stg + ((lane & 7) + ((lane >> 4) << 3)) * KST + (((lane >> 3) & 1) << 4);
#pragma unroll
            for (int ks = 0; ks < 4; ks++)
#pragma unroll
                for (int nip = 0; nip < 4; nip++) {
                    unsigned bf4[4];
                    ldsm4(bf4, kb4 + nip * (16 * KST) + ks * 32);
                    mma_f16(s[2*nip],   qf[ks], bf4);
                    mma_f16(s[2*nip+1], qf[ks], bf4 + 2);
                }
            // ---- causal mask ----
            if (k0 + 63 > qr0) {
#pragma unroll
                for (int ni = 0; ni < 8; ni++) {
                    int kc = k0 + ni * 8 + t * 2;
                    if (kc     > qr0)     s[ni][0] = -1e30f;
                    if (kc + 1 > qr0)     s[ni][1] = -1e30f;
                    if (kc     > qr0 + 8) s[ni][2] = -1e30f;
                    if (kc + 1 > qr0 + 8) s[ni][3] = -1e30f;
                }
            }
            // ---- online max (warp-local, rows g and g+8) ----
            float bm0 = -1e30f, bm1 = -1e30f;
#pragma unroll
            for (int ni = 0; ni < 8; ni++) {
                bm0 = fmaxf(bm0, fmaxf(s[ni][0], s[ni][1]));
                bm1 = fmaxf(bm1, fmaxf(s[ni][2], s[ni][3]));
            }
            bm0 = fmaxf(bm0, __shfl_xor_sync(0xffffffffu, bm0, 1));
            bm0 = fmaxf(bm0, __shfl_xor_sync(0xffffffffu, bm0, 2));
            bm1 = fmaxf(bm1, __shfl_xor_sync(0xffffffffu, bm1, 1));
            bm1 = fmaxf(bm1, __shfl_xor_sync(0xffffffffu, bm1, 2));
            float mn0 = fmaxf(m0, bm0), mn1 = fmaxf(m1, bm1);
            float a0 = ex2f(m0 - mn0), a1 = ex2f(m1 - mn1);
            m0 = mn0; m1 = mn1;
#pragma unroll
            for (int ni = 0; ni < 8; ni++) {
                o[ni][0] *= a0; o[ni][1] *= a0;
                o[ni][2] *= a1; o[ni][3] *= a1;
            }
            oc[0] *= a0; oc[1] *= a0; oc[2] *= a1; oc[3] *= a1;
            // ---- O += P * V;  P = ex2.f16x2(S - m) built in-loop ----
            unsigned vb4 = stg + KV_TILE + (lane & 15) * KST + ((lane >> 4) << 4);
#pragma unroll
            for (int ks = 0; ks < 4; ks++) {
                int i0 = 2 * ks, i1 = 2 * ks + 1;
                unsigned aP[4] = {
                    h2ex2(s[i0][0] - m0, s[i0][1] - m0),
                    h2ex2(s[i0][2] - m1, s[i0][3] - m1),
                    h2ex2(s[i1][0] - m0, s[i1][1] - m0),
                    h2ex2(s[i1][2] - m1, s[i1][3] - m1)
                };
#pragma unroll
                for (int nip = 0; nip < 4; nip++) {
                    unsigned bv[4];
                    ldsm4t(bv, vb4 + ks * (16 * KST) + nip * 32);
                    mma_f16(o[2*nip],   aP, bv);
                    mma_f16(o[2*nip+1], aP, bv + 2);
                }
                mma_f16(oc, aP, bones);   // l accumulation via ones column
            }
        }
        __syncthreads();
    }

    // ---- finalize: l from ones-column (t=0 lane of each quad), O/l, fp16 out ----
    float l0 = __shfl_sync(0xffffffffu, oc[0], lane & 28);
    float l1 = __shfl_sync(0xffffffffu, oc[2], lane & 28);
    float inv0 = 1.0f / l0, inv1 = 1.0f / l1;
    size_t r0off = (size_t)(b * POS + qr0) * DM + h * DH;
    size_t r1off = r0off + (size_t)8 * DM;
#pragma unroll
    for (int ni = 0; ni < 8; ni++) {
        int col = ni * 8 + t * 2;
        *(__half2*)(g_Af + r0off + col) = __floats2half2_rn(o[ni][0] * inv0, o[ni][1] * inv0);
        *(__half2*)(g_Af + r1off + col) = __floats2half2_rn(o[ni][2] * inv1, o[ni][3] * inv1);
    }
}

// ---------------- launch ----------------
extern "C" void kernel_launch(void* const* d_in, const int* in_sizes, int n_in,
                              void* d_out, int out_size)
{
    (void)in_sizes; (void)n_in; (void)out_size;
    const float* X  = (const float*)d_in[0];
    const float* Wq = (const float*)d_in[1];
    const float* Wk = (const float*)d_in[2];
    const float* Wv = (const float*)d_in[3];
    const float* Wo = (const float*)d_in[4];
    float* out = (float*)d_out;

    __half *Xf, *Qf, *Kf, *Vf, *Af, *Wqf, *Wkf, *Wvf, *Wof;
    cudaGetSymbolAddress((void**)&Xf,  g_Xf);
    cudaGetSymbolAddress((void**)&Qf,  g_Qf);
    cudaGetSymbolAddress((void**)&Kf,  g_Kf);
    cudaGetSymbolAddress((void**)&Vf,  g_Vf);
    cudaGetSymbolAddress((void**)&Af,  g_Af);
    cudaGetSymbolAddress((void**)&Wqf, g_Wqf);
    cudaGetSymbolAddress((void**)&Wkf, g_Wkf);
    cudaGetSymbolAddress((void**)&Wvf, g_Wvf);
    cudaGetSymbolAddress((void**)&Wof, g_Wof);

    cudaFuncSetAttribute(mma_gemm<0>, cudaFuncAttributeMaxDynamicSharedMemorySize, GEMM_SMEM_BYTES);
    cudaFuncSetAttribute(mma_gemm<1>, cudaFuncAttributeMaxDynamicSharedMemorySize, GEMM_SMEM_BYTES);
    cudaFuncSetAttribute(attn_mma,    cudaFuncAttributeMaxDynamicSharedMemorySize, ATTN_SMEM);

    // 0) fp16 conversions
    int n4 = TOK * DM / 4;
    cvt_x<<<(n4 + 255) / 256, 256>>>((const float4*)X, (__half2*)Xf, n4);
    dim3 gw(DM / 32, DM / 32, 4);
    cvt_w_all<<<gw, 1024>>>(Wq, Wk, Wv, Wo, Wqf, Wkf, Wvf, Wof);

    // 1) fused QKV projection (fp16) -> fp16 Q (pre-scaled), K, V
    dim3 g1(DM / 128, TOK / 128, 3);
    mma_gemm<0><<<g1, 256, GEMM_SMEM_BYTES>>>(Xf, Wqf, Wkf, Wvf, nullptr, Qf, Kf, Vf);

    // 2) causal flash attention (fp16, log2-domain softmax) -> fp16 A
    dim3 g2(POS / AQ, HEADS, BATCH);
    attn_mma<<<g2, 256, ATTN_SMEM>>>();

    // 3) out projection (fp16) -> fp32 output
    dim3 g3(DM / 128, TOK / 128, 1);
    mma_gemm<1><<<g3, 256, GEMM_SMEM_BYTES>>>(Af, Wof, nullptr, nullptr, out, nullptr, nullptr, nullptr);
}